// round 4
// baseline (speedup 1.0000x reference)
#include <cuda_runtime.h>
#include <cfloat>
#include <math.h>

#define M_TOT 16384   // B*N queries
#define D_IN  1024
#define E_DIM 512
#define K_CB  4096

// Scratch (device globals: no allocation allowed)
__device__ float g_xn[M_TOT * E_DIM];   // proj, then normalized rows (in place)
__device__ float g_cn[K_CB * E_DIM];    // normalized codebook
__device__ float g_cnn[K_CB];           // sum(cn*cn) per codeword

// ---------------------------------------------------------------------------
// Kernel 1: projection GEMM  g_xn[M,E] = X[M,D] @ W[D,E]
// ---------------------------------------------------------------------------
__global__ void proj_gemm_kernel(const float* __restrict__ X,
                                 const float* __restrict__ W) {
    __shared__ float As[16 * 132];   // [k][m], padded
    __shared__ float Bs[16 * 64];    // [k][n]
    const int tx = threadIdx.x & 15;
    const int ty = threadIdx.x >> 4;
    const int m0 = blockIdx.y * 128;
    const int n0 = blockIdx.x * 64;

    float acc[8][4];
    #pragma unroll
    for (int i = 0; i < 8; i++)
        #pragma unroll
        for (int j = 0; j < 4; j++) acc[i][j] = 0.0f;

    for (int kt = 0; kt < D_IN; kt += 16) {
        #pragma unroll
        for (int t = 0; t < 2; t++) {
            int f   = threadIdx.x * 2 + t;   // 0..511
            int row = f >> 2;                // 0..127
            int c4  = f & 3;                 // 0..3
            float4 v = *(const float4*)(X + (size_t)(m0 + row) * D_IN + kt + c4 * 4);
            As[(c4 * 4 + 0) * 132 + row] = v.x;
            As[(c4 * 4 + 1) * 132 + row] = v.y;
            As[(c4 * 4 + 2) * 132 + row] = v.z;
            As[(c4 * 4 + 3) * 132 + row] = v.w;
        }
        {
            int f  = threadIdx.x;            // 0..255
            int k  = f >> 4;
            int c4 = f & 15;
            float4 v = *(const float4*)(W + (size_t)(kt + k) * E_DIM + n0 + c4 * 4);
            *(float4*)(Bs + k * 64 + c4 * 4) = v;
        }
        __syncthreads();

        #pragma unroll
        for (int k = 0; k < 16; k++) {
            float4 a0 = *(const float4*)(As + k * 132 + ty * 8);
            float4 a1 = *(const float4*)(As + k * 132 + ty * 8 + 4);
            float4 b  = *(const float4*)(Bs + k * 64 + tx * 4);
            float a[8] = {a0.x, a0.y, a0.z, a0.w, a1.x, a1.y, a1.z, a1.w};
            float bb[4] = {b.x, b.y, b.z, b.w};
            #pragma unroll
            for (int i = 0; i < 8; i++)
                #pragma unroll
                for (int j = 0; j < 4; j++)
                    acc[i][j] = fmaf(a[i], bb[j], acc[i][j]);
        }
        __syncthreads();
    }

    #pragma unroll
    for (int i = 0; i < 8; i++) {
        float4 v = make_float4(acc[i][0], acc[i][1], acc[i][2], acc[i][3]);
        *(float4*)(g_xn + (size_t)(m0 + ty * 8 + i) * E_DIM + n0 + tx * 4) = v;
    }
}

// ---------------------------------------------------------------------------
// Kernel 2: normalize rows of g_xn in place
// ---------------------------------------------------------------------------
__global__ void norm_x_kernel() {
    const int row = blockIdx.x;
    float* p = g_xn + (size_t)row * E_DIM;
    float4 v = *(float4*)(p + threadIdx.x * 4);
    float s = v.x * v.x + v.y * v.y + v.z * v.z + v.w * v.w;
    #pragma unroll
    for (int o = 16; o > 0; o >>= 1) s += __shfl_xor_sync(0xFFFFFFFFu, s, o);
    __shared__ float ws[4];
    if ((threadIdx.x & 31) == 0) ws[threadIdx.x >> 5] = s;
    __syncthreads();
    float tot = ws[0] + ws[1] + ws[2] + ws[3];
    float denom = fmaxf(sqrtf(tot), 1e-12f);
    v.x = v.x / denom; v.y = v.y / denom; v.z = v.z / denom; v.w = v.w / denom;
    *(float4*)(p + threadIdx.x * 4) = v;
}

// ---------------------------------------------------------------------------
// Kernel 3: normalize codebook -> g_cn, g_cnn = sum(cn*cn) per row
// ---------------------------------------------------------------------------
__global__ void norm_cb_kernel(const float* __restrict__ CB) {
    const int row = blockIdx.x;
    float4 v = *(const float4*)(CB + (size_t)row * E_DIM + threadIdx.x * 4);
    float s = v.x * v.x + v.y * v.y + v.z * v.z + v.w * v.w;
    #pragma unroll
    for (int o = 16; o > 0; o >>= 1) s += __shfl_xor_sync(0xFFFFFFFFu, s, o);
    __shared__ float ws[4];
    __shared__ float ws2[4];
    if ((threadIdx.x & 31) == 0) ws[threadIdx.x >> 5] = s;
    __syncthreads();
    float tot = ws[0] + ws[1] + ws[2] + ws[3];
    float denom = fmaxf(sqrtf(tot), 1e-12f);
    v.x = v.x / denom; v.y = v.y / denom; v.z = v.z / denom; v.w = v.w / denom;
    *(float4*)(g_cn + (size_t)row * E_DIM + threadIdx.x * 4) = v;
    float s2 = v.x * v.x + v.y * v.y + v.z * v.z + v.w * v.w;
    #pragma unroll
    for (int o = 16; o > 0; o >>= 1) s2 += __shfl_xor_sync(0xFFFFFFFFu, s2, o);
    if ((threadIdx.x & 31) == 0) ws2[threadIdx.x >> 5] = s2;
    __syncthreads();
    if (threadIdx.x == 0) g_cnn[row] = ws2[0] + ws2[1] + ws2[2] + ws2[3];
}

// ---------------------------------------------------------------------------
// Kernel 4 (fast path): argmax_k ( <cn_k,xn_q> - cnn[k]/2 ) == argmin distance
// 64 queries/block, 256 blocks, 155 KB dynamic smem (opt-in).
// Output written as FLOAT values of the indices (harness output dtype).
// ---------------------------------------------------------------------------
#define XS_PITCH 65
#define CS_PITCH 132
#define SMEM_BYTES ((512 * XS_PITCH + 32 * CS_PITCH + 128 + 64 * 16) * 4 + 64 * 16 * 4)

__global__ void argmin_kernel(float* __restrict__ out) {
    extern __shared__ float sm[];
    float* xs   = sm;                          // [512][65]  xs[e][q]
    float* cs   = xs + 512 * XS_PITCH;         // [32][132]  cs[e][k]
    float* cnns = cs + 32 * CS_PITCH;          // [128]
    float* rv   = cnns + 128;                  // [64][16]
    int*   ri   = (int*)(rv + 64 * 16);        // [64][16]

    const int tx = threadIdx.x & 15;
    const int ty = threadIdx.x >> 4;
    const int q0 = blockIdx.x * 64;

    #pragma unroll 4
    for (int t = 0; t < 32; t++) {
        int f = threadIdx.x + t * 256;     // 0..8191
        int q = f >> 7;                    // 0..63
        int e4 = f & 127;                  // 0..127
        float4 v = *(const float4*)(g_xn + (size_t)(q0 + q) * E_DIM + e4 * 4);
        xs[(e4 * 4 + 0) * XS_PITCH + q] = v.x;
        xs[(e4 * 4 + 1) * XS_PITCH + q] = v.y;
        xs[(e4 * 4 + 2) * XS_PITCH + q] = v.z;
        xs[(e4 * 4 + 3) * XS_PITCH + q] = v.w;
    }
    __syncthreads();

    float bestv[4] = {-INFINITY, -INFINITY, -INFINITY, -INFINITY};
    int   besti[4] = {0, 0, 0, 0};

    for (int kc = 0; kc < K_CB; kc += 128) {
        __syncthreads();
        if (threadIdx.x < 128) cnns[threadIdx.x] = g_cnn[kc + threadIdx.x];

        float acc[4][8];
        #pragma unroll
        for (int i = 0; i < 4; i++)
            #pragma unroll
            for (int j = 0; j < 8; j++) acc[i][j] = 0.0f;

        for (int et = 0; et < 16; et++) {
            #pragma unroll
            for (int t = 0; t < 4; t++) {
                int f  = threadIdx.x + t * 256;  // 0..1023
                int k  = f >> 3;                 // 0..127
                int e4 = f & 7;                  // 0..7
                float4 v = *(const float4*)(g_cn + (size_t)(kc + k) * E_DIM + et * 32 + e4 * 4);
                cs[(e4 * 4 + 0) * CS_PITCH + k] = v.x;
                cs[(e4 * 4 + 1) * CS_PITCH + k] = v.y;
                cs[(e4 * 4 + 2) * CS_PITCH + k] = v.z;
                cs[(e4 * 4 + 3) * CS_PITCH + k] = v.w;
            }
            __syncthreads();

            #pragma unroll
            for (int e = 0; e < 32; e++) {
                const int eg = et * 32 + e;
                float xa[4];
                #pragma unroll
                for (int i = 0; i < 4; i++) xa[i] = xs[eg * XS_PITCH + ty * 4 + i];
                float4 c0 = *(const float4*)(cs + e * CS_PITCH + tx * 4);
                float4 c1 = *(const float4*)(cs + e * CS_PITCH + 64 + tx * 4);
                float cb[8] = {c0.x, c0.y, c0.z, c0.w, c1.x, c1.y, c1.z, c1.w};
                #pragma unroll
                for (int i = 0; i < 4; i++)
                    #pragma unroll
                    for (int j = 0; j < 8; j++)
                        acc[i][j] = fmaf(xa[i], cb[j], acc[i][j]);
            }
            __syncthreads();
        }

        #pragma unroll
        for (int i = 0; i < 4; i++) {
            #pragma unroll
            for (int j = 0; j < 8; j++) {
                int kk = (j < 4) ? (tx * 4 + j) : (64 + tx * 4 + (j - 4));
                float s = acc[i][j] - 0.5f * cnns[kk];
                if (s > bestv[i]) { bestv[i] = s; besti[i] = kc + kk; }
            }
        }
    }

    __syncthreads();
    #pragma unroll
    for (int i = 0; i < 4; i++) {
        int q = ty * 4 + i;
        rv[q * 16 + tx] = bestv[i];
        ri[q * 16 + tx] = besti[i];
    }
    __syncthreads();
    if (threadIdx.x < 64) {
        int q = threadIdx.x;
        float bv = rv[q * 16];
        int   bi = ri[q * 16];
        #pragma unroll
        for (int t = 1; t < 16; t++) {
            float v  = rv[q * 16 + t];
            int   ix = ri[q * 16 + t];
            if (v > bv || (v == bv && ix < bi)) { bv = v; bi = ix; }
        }
        out[q0 + q] = (float)bi;   // output dtype: float32
    }
}

// ---------------------------------------------------------------------------
// Kernel 4 (fallback): 16 queries/block, 44 KB STATIC shared memory.
// ---------------------------------------------------------------------------
__global__ void argmin_small_kernel(float* __restrict__ out) {
    __shared__ float xs[512 * 16];
    __shared__ float cs[4 * 512];
    __shared__ float cnns[512];
    __shared__ float rv2[8 * 4];
    __shared__ int   ri2[8 * 4];

    const int tid = threadIdx.x;
    const int tx  = tid & 63;
    const int ty  = tid >> 6;
    const int lane = tid & 31;
    const int wid  = tid >> 5;
    const int q0 = blockIdx.x * 16;

    #pragma unroll
    for (int t = 0; t < 8; t++) {
        int f = tid + t * 256;
        int q = f >> 7;
        int e4 = f & 127;
        float4 v = *(const float4*)(g_xn + (size_t)(q0 + q) * E_DIM + e4 * 4);
        xs[(e4 * 4 + 0) * 16 + q] = v.x;
        xs[(e4 * 4 + 1) * 16 + q] = v.y;
        xs[(e4 * 4 + 2) * 16 + q] = v.z;
        xs[(e4 * 4 + 3) * 16 + q] = v.w;
    }
    __syncthreads();

    float bestv[4] = {-INFINITY, -INFINITY, -INFINITY, -INFINITY};
    int   besti[4] = {0, 0, 0, 0};

    for (int kc = 0; kc < K_CB; kc += 512) {
        __syncthreads();
        cnns[tid]       = g_cnn[kc + tid];
        cnns[tid + 256] = g_cnn[kc + tid + 256];

        float acc[4][8];
        #pragma unroll
        for (int i = 0; i < 4; i++)
            #pragma unroll
            for (int j = 0; j < 8; j++) acc[i][j] = 0.0f;

        for (int et = 0; et < 128; et++) {
            #pragma unroll
            for (int t = 0; t < 2; t++) {
                int k = tid + t * 256;
                float4 v = *(const float4*)(g_cn + (size_t)(kc + k) * E_DIM + et * 4);
                cs[0 * 512 + k] = v.x;
                cs[1 * 512 + k] = v.y;
                cs[2 * 512 + k] = v.z;
                cs[3 * 512 + k] = v.w;
            }
            __syncthreads();

            #pragma unroll
            for (int e = 0; e < 4; e++) {
                const int eg = et * 4 + e;
                float xa[4];
                #pragma unroll
                for (int i = 0; i < 4; i++) xa[i] = xs[eg * 16 + ty * 4 + i];
                float4 c0 = *(const float4*)(cs + e * 512 + tx * 8);
                float4 c1 = *(const float4*)(cs + e * 512 + tx * 8 + 4);
                float cb[8] = {c0.x, c0.y, c0.z, c0.w, c1.x, c1.y, c1.z, c1.w};
                #pragma unroll
                for (int i = 0; i < 4; i++)
                    #pragma unroll
                    for (int j = 0; j < 8; j++)
                        acc[i][j] = fmaf(xa[i], cb[j], acc[i][j]);
            }
            __syncthreads();
        }

        #pragma unroll
        for (int i = 0; i < 4; i++) {
            #pragma unroll
            for (int j = 0; j < 8; j++) {
                int kk = tx * 8 + j;
                float s = acc[i][j] - 0.5f * cnns[kk];
                if (s > bestv[i]) { bestv[i] = s; besti[i] = kc + kk; }
            }
        }
    }

    #pragma unroll
    for (int i = 0; i < 4; i++) {
        float v = bestv[i]; int ix = besti[i];
        #pragma unroll
        for (int o = 16; o > 0; o >>= 1) {
            float ov = __shfl_xor_sync(0xFFFFFFFFu, v, o);
            int   oi = __shfl_xor_sync(0xFFFFFFFFu, ix, o);
            if (ov > v || (ov == v && oi < ix)) { v = ov; ix = oi; }
        }
        if (lane == 0) { rv2[wid * 4 + i] = v; ri2[wid * 4 + i] = ix; }
    }
    __syncthreads();
    if (tid < 16) {
        int tg = tid >> 2;
        int i  = tid & 3;
        int w0 = tg * 2, w1 = tg * 2 + 1;
        float v0 = rv2[w0 * 4 + i]; int i0 = ri2[w0 * 4 + i];
        float v1 = rv2[w1 * 4 + i]; int i1 = ri2[w1 * 4 + i];
        int bi = (v1 > v0 || (v1 == v0 && i1 < i0)) ? i1 : i0;
        out[q0 + tg * 4 + i] = (float)bi;   // output dtype: float32
    }
}

// ---------------------------------------------------------------------------
extern "C" void kernel_launch(void* const* d_in, const int* in_sizes, int n_in,
                              void* d_out, int out_size) {
    const float* x  = nullptr;
    const float* w  = nullptr;
    const float* cb = nullptr;
    for (int i = 0; i < n_in; i++) {
        if (in_sizes[i] == M_TOT * D_IN)       x  = (const float*)d_in[i];
        else if (in_sizes[i] == D_IN * E_DIM)  w  = (const float*)d_in[i];
        else if (in_sizes[i] == K_CB * E_DIM)  cb = (const float*)d_in[i];
    }
    float* out = (float*)d_out;

    dim3 g1(E_DIM / 64, M_TOT / 128);   // (8, 128)
    proj_gemm_kernel<<<g1, 256>>>(x, w);
    norm_x_kernel<<<M_TOT, 128>>>();
    norm_cb_kernel<<<K_CB, 128>>>(cb);

    cudaError_t aerr = cudaFuncSetAttribute(
        argmin_kernel, cudaFuncAttributeMaxDynamicSharedMemorySize, SMEM_BYTES);
    if (aerr == cudaSuccess) {
        argmin_kernel<<<M_TOT / 64, 256, SMEM_BYTES>>>(out);
    } else {
        argmin_small_kernel<<<M_TOT / 16, 256>>>(out);
    }
}